// round 15
// baseline (speedup 1.0000x reference)
#include <cuda_runtime.h>
#include <stdint.h>

#define NUM_TNETS 8388608
#define NUM_NODES 1048576

// FINAL — at the LTS transaction roofline. 1 tnet/thread + cache hints.
// Measured 152.1us (ties the global best across 14 rounds of shape search).
//
// Floor model: 33.5M REDG.ADD (random 4B targets, 4MB L2-resident output)
//            + 16.7M gather sectors (random 4B over the 84MB pin2node table)
//            + ~3M streaming sectors (96MB pins+weights, evict-first)
//            = ~53M LTS transactions / 184 slices = 288K cyc ~= 152us.
// ncu: L2=83% binding; DRAM=38%, issue=3.6%, occ=86% — all slack.
//
// Complete shape matrix (all measured):
//   1 tnet no hints 164.9 | 2 tnet+hints 152.0 | 4 tnet+hints 155.5
//   512-thr 153.7 | persistent 170.2 | 1 tnet+hints 152.1  <- this
// Every saturating shape lands in the 152-154 band = ~98% of the slot floor.
// The win over the naive kernel is the cache policy, not the packaging:
// .cs on streams keeps the gather table L2-resident; .cg skips useless L1
// allocation on the random gathers.
__global__ void __launch_bounds__(256) scatter_add_kernel(
    const float* __restrict__ beta,          // [1]
    const float* __restrict__ tnet_weights,  // [NUM_TNETS]
    const int*   __restrict__ flat_tnet2pin, // [2*NUM_TNETS] int32
    const int*   __restrict__ pin2node,      // [NUM_PINS]    int32
    float* __restrict__ out)                 // [NUM_NODES]
{
    int t = blockIdx.x * blockDim.x + threadIdx.x;  // one tnet per thread

    // coalesced 8B streaming load: this arc's (src, dst) pins
    int2 pins = __ldcs(reinterpret_cast<const int2*>(flat_tnet2pin) + t);
    // coalesced 4B streaming load: the arc weight, beta folded in
    float w = __ldcs(tnet_weights + t) * __ldg(beta);

    // two independent random gathers, L2-only
    int n0 = __ldcg(pin2node + pins.x);
    int n1 = __ldcg(pin2node + pins.y);

    atomicAdd(out + n0, w);
    atomicAdd(out + n1, w);
}

extern "C" void kernel_launch(void* const* d_in, const int* in_sizes, int n_in,
                              void* d_out, int out_size) {
    const float* beta         = (const float*)d_in[0];
    const float* tnet_weights = (const float*)d_in[1];
    const int*   flat_t2p     = (const int*)d_in[2];
    const int*   pin2node     = (const int*)d_in[3];
    float* out = (float*)d_out;

    // 1) zero the poisoned output (~0.7us, under the noise floor)
    cudaMemsetAsync(out, 0, (size_t)out_size * sizeof(float));

    // 2) gather + atomic scatter-add
    {
        const int threads = 256;
        const int blocks = NUM_TNETS / threads;   // 32768 exact
        scatter_add_kernel<<<blocks, threads>>>(beta, tnet_weights, flat_t2p,
                                                pin2node, out);
    }
}

// round 16
// speedup vs baseline: 1.0046x; 1.0046x over previous
#include <cuda_runtime.h>
#include <stdint.h>

#define NUM_TNETS 8388608
#define NUM_NODES 1048576

// FINAL — at the LTS transaction roofline. 1 tnet/thread + cache hints.
// Band: 152.0-154.1us over 10 consecutive saturating-shape runs.
//
// Floor model: 33.5M REDG.ADD (random 4B targets, 4MB L2-resident output)
//            + 16.7M gather sectors (random 4B over the 84MB pin2node table)
//            + ~3M streaming sectors (96MB pins+weights, evict-first)
//            = ~53M LTS transactions / 184 slices = 288K cyc ~= 152us.
// ncu: L2=83% binding; DRAM=38%, issue=3.6%, occ=87% — all slack.
//
// Complete shape matrix (all measured):
//   1 tnet no hints 164.9 | 2 tnet+hints 152.0 | 4 tnet+hints 155.5
//   512-thr 153.7 | persistent 170.2 | 1 tnet+hints 152.1  <- this
// The win over naive is the cache policy, not packaging: .cs on streams
// keeps the gather table L2-resident; .cg skips useless L1 allocation on
// the random gathers. Transaction count is algorithmically irreducible.
__global__ void __launch_bounds__(256) scatter_add_kernel(
    const float* __restrict__ beta,          // [1]
    const float* __restrict__ tnet_weights,  // [NUM_TNETS]
    const int*   __restrict__ flat_tnet2pin, // [2*NUM_TNETS] int32
    const int*   __restrict__ pin2node,      // [NUM_PINS]    int32
    float* __restrict__ out)                 // [NUM_NODES]
{
    int t = blockIdx.x * blockDim.x + threadIdx.x;  // one tnet per thread

    // coalesced 8B streaming load: this arc's (src, dst) pins
    int2 pins = __ldcs(reinterpret_cast<const int2*>(flat_tnet2pin) + t);
    // coalesced 4B streaming load: the arc weight, beta folded in
    float w = __ldcs(tnet_weights + t) * __ldg(beta);

    // two independent random gathers, L2-only
    int n0 = __ldcg(pin2node + pins.x);
    int n1 = __ldcg(pin2node + pins.y);

    atomicAdd(out + n0, w);
    atomicAdd(out + n1, w);
}

extern "C" void kernel_launch(void* const* d_in, const int* in_sizes, int n_in,
                              void* d_out, int out_size) {
    const float* beta         = (const float*)d_in[0];
    const float* tnet_weights = (const float*)d_in[1];
    const int*   flat_t2p     = (const int*)d_in[2];
    const int*   pin2node     = (const int*)d_in[3];
    float* out = (float*)d_out;

    // 1) zero the poisoned output (~0.7us, under the noise floor)
    cudaMemsetAsync(out, 0, (size_t)out_size * sizeof(float));

    // 2) gather + atomic scatter-add
    {
        const int threads = 256;
        const int blocks = NUM_TNETS / threads;   // 32768 exact
        scatter_add_kernel<<<blocks, threads>>>(beta, tnet_weights, flat_t2p,
                                                pin2node, out);
    }
}